// round 10
// baseline (speedup 1.0000x reference)
#include <cuda_runtime.h>
#include <math.h>

typedef unsigned long long u64;

#define T_    2048
#define NB_   64
#define NU_   8
#define NH_   256
#define H2_   128
#define NY_   8
#define S_    32
#define L_    64           // T_/S_
#define NSQ_  6            // log2(L_)
#define NBP_  32           // NB_/2 (batch pairs)
#define CH_   8            // chunk of timesteps (k_main)
#define NCH_  8            // L_/CH_
#define CHS_  16           // chunk of timesteps (k_seg)
#define NCHS_ 4            // L_/CHS_
#define XROW_ 256          // Xs row (u64); no padding needed (all accesses contiguous)

// scratch (device globals; no allocation allowed)
__device__ u64 g_final[S_][NBP_][H2_][2];
__device__ u64 g_init [S_][NBP_][H2_][2];

// precomputed constants (k_pre)
__device__ float2 g_lam [H2_];     // lambda
__device__ float2 g_lam2[H2_];     // lambda^2
__device__ float2 g_lamL[H2_];     // lambda^L
__device__ float  g_B1[H2_][NU_];  // B[h]   * exp(mB[h])
__device__ float  g_B2[H2_][NU_];  // B[h+H2]* exp(mB[h+H2])
__device__ float  g_C1[H2_][NU_];  // re*B1 - im*B2
__device__ float  g_C2[H2_][NU_];  // im*B1 + re*B2
// splatted u64 copies for cheap per-chunk reload in k_main (16B aligned rows)
__device__ __align__(16) u64 g_B1p[H2_][NU_];
__device__ __align__(16) u64 g_B2p[H2_][NU_];

// ---- packed f32x2 helpers (Blackwell FFMA2 path) ----
static __device__ __forceinline__ u64 pk2(float lo, float hi) {
    u64 r; asm("mov.b64 %0, {%1,%2};" : "=l"(r) : "f"(lo), "f"(hi)); return r;
}
static __device__ __forceinline__ void upk2(u64 v, float& lo, float& hi) {
    asm("mov.b64 {%0,%1}, %2;" : "=f"(lo), "=f"(hi) : "l"(v));
}
static __device__ __forceinline__ u64 ffma2(u64 a, u64 b, u64 c) {
    u64 d; asm("fma.rn.f32x2 %0,%1,%2,%3;" : "=l"(d) : "l"(a), "l"(b), "l"(c)); return d;
}
static __device__ __forceinline__ u64 fmul2(u64 a, u64 b) {
    u64 d; asm("mul.rn.f32x2 %0,%1,%2;" : "=l"(d) : "l"(a), "l"(b)); return d;
}
static __device__ __forceinline__ u64 fadd2(u64 a, u64 b) {
    u64 d; asm("add.rn.f32x2 %0,%1,%2;" : "=l"(d) : "l"(a), "l"(b)); return d;
}
static __device__ __forceinline__ u64 splat(float v) { return pk2(v, v); }

// =====================================================================
// Kernel 0: one-time constant precompute (all DP math lives here)
// grid 8 x 16 threads (spread DP across SMs)
// =====================================================================
__global__ void k_pre(
    const float* __restrict__ lr, const float* __restrict__ li,
    const float* __restrict__ B, const float* __restrict__ mB)
{
    const int h = blockIdx.x * 16 + threadIdx.x;
    double e1 = exp((double)mB[h]);
    double e2 = exp((double)mB[h + H2_]);
    double r  = exp(-fabs((double)lr[h]));
    double th = 1.5707963267948966 * (double)li[h];
    double re = r * cos(th);
    double im = r * sin(th);
    g_lam[h]  = make_float2((float)re, (float)im);
    g_lam2[h] = make_float2((float)(re * re - im * im), (float)(2.0 * re * im));
    double pr = re, pi = im;
#pragma unroll
    for (int i = 0; i < NSQ_; ++i) {
        double nr = pr * pr - pi * pi;
        double ni = 2.0 * pr * pi;
        pr = nr; pi = ni;
    }
    g_lamL[h] = make_float2((float)pr, (float)pi);
#pragma unroll
    for (int u = 0; u < NU_; ++u) {
        double b1 = (double)B[h * NU_ + u] * e1;
        double b2 = (double)B[(h + H2_) * NU_ + u] * e2;
        float b1f = (float)b1, b2f = (float)b2;
        g_B1[h][u] = b1f;
        g_B2[h][u] = b2f;
        g_B1p[h][u] = pk2(b1f, b1f);
        g_B2p[h][u] = pk2(b2f, b2f);
        g_C1[h][u] = (float)(re * b1 - im * b2);
        g_C2[h][u] = (float)(im * b1 + re * b2);
    }
}

// =====================================================================
// Kernel 1: per-segment local scan (zero init, 2-step fused) -> g_final
// =====================================================================
__global__ void __launch_bounds__(128, 4) k_seg(const float* __restrict__ U)
{
    const int h  = threadIdx.x;
    const int bp = blockIdx.x;
    const int s  = blockIdx.y;
    const int b0 = bp << 1;

    u64 B1s[NU_], B2s[NU_], C1s[NU_], C2s[NU_];
#pragma unroll
    for (int u = 0; u < NU_; ++u) {
        B1s[u] = splat(g_B1[h][u]);
        B2s[u] = splat(g_B2[h][u]);
        C1s[u] = splat(g_C1[h][u]);
        C2s[u] = splat(g_C2[h][u]);
    }
    float2 l2 = g_lam2[h];
    u64 R2 = splat(l2.x), I2 = splat(l2.y), nI2 = splat(-l2.y);

    u64 x1 = 0ull, x2 = 0ull;

    __shared__ __align__(16) u64 Us[CHS_][NU_];
    const float* Ub = U + ((size_t)s * L_ * NB_ + b0) * NU_;

    for (int c = 0; c < NCHS_; ++c) {
        __syncthreads();
        {
            int t = h >> 3, u = h & 7;
            const float* p = Ub + (size_t)(c * CHS_ + t) * (NB_ * NU_) + u;
            Us[t][u] = pk2(p[0], p[NU_]);
        }
        __syncthreads();
#pragma unroll
        for (int i = 0; i < CHS_ / 2; ++i) {
            const ulonglong2* pa = (const ulonglong2*)(&Us[2 * i][0]);
            ulonglong2 a0 = pa[0], a1 = pa[1], a2 = pa[2], a3 = pa[3];
            const ulonglong2* pb = (const ulonglong2*)(&Us[2 * i + 1][0]);
            ulonglong2 bq0 = pb[0], bq1 = pb[1], bq2 = pb[2], bq3 = pb[3];
            u64 uA[8] = { a0.x, a0.y, a1.x, a1.y, a2.x, a2.y, a3.x, a3.y };
            u64 uB[8] = { bq0.x, bq0.y, bq1.x, bq1.y, bq2.x, bq2.y, bq3.x, bq3.y };

            u64 p1 = fmul2(C1s[0], uA[0]);
            u64 q1 = fmul2(B1s[0], uB[0]);
            u64 p2 = fmul2(C2s[0], uA[0]);
            u64 q2 = fmul2(B2s[0], uB[0]);
#pragma unroll
            for (int u = 1; u < NU_; ++u) {
                p1 = ffma2(C1s[u], uA[u], p1);
                q1 = ffma2(B1s[u], uB[u], q1);
                p2 = ffma2(C2s[u], uA[u], p2);
                q2 = ffma2(B2s[u], uB[u], q2);
            }
            u64 acc1 = fadd2(p1, q1);
            u64 acc2 = fadd2(p2, q2);

            u64 nx1 = ffma2(R2, x1, ffma2(nI2, x2, acc1));
            u64 nx2 = ffma2(I2, x1, ffma2(R2, x2, acc2));
            x1 = nx1; x2 = nx2;
        }
    }
    g_final[s][bp][h][0] = x1;
    g_final[s][bp][h][1] = x2;
}

// =====================================================================
// Kernel 2: sequential combine across segments -> g_init
// =====================================================================
__global__ void __launch_bounds__(128, 1) k_comb(
    const float* __restrict__ y0,
    const float* __restrict__ Wyx, const float* __restrict__ byx)
{
    const int h  = threadIdx.x;
    const int bp = blockIdx.x;
    const int b0 = bp << 1;

    float2 lL = g_lamL[h];
    u64 pr2 = splat(lL.x), pi2 = splat(lL.y), npi2 = splat(-lL.y);

    u64 z1 = splat(byx[h]), z2 = splat(byx[h + H2_]);
#pragma unroll
    for (int y = 0; y < NY_; ++y) {
        u64 yv = pk2(y0[b0 * NY_ + y], y0[(b0 + 1) * NY_ + y]);
        z1 = ffma2(splat(Wyx[h * NY_ + y]), yv, z1);
        z2 = ffma2(splat(Wyx[(h + H2_) * NY_ + y]), yv, z2);
    }
#pragma unroll
    for (int s = 0; s < S_; ++s) {
        g_init[s][bp][h][0] = z1;
        g_init[s][bp][h][1] = z2;
        u64 f1 = g_final[s][bp][h][0];
        u64 f2 = g_final[s][bp][h][1];
        u64 n1 = ffma2(pr2, z1, ffma2(npi2, z2, f1));
        u64 n2 = ffma2(pr2, z2, ffma2(pi2,  z1, f2));
        z1 = n1; z2 = n2;
    }
}

// =====================================================================
// Kernel 3: re-scan with correct init + fused Y projection
// grid (NBP_, S_), 128 threads, dynamic shared
// shared (u64): Xs[CH_][XROW_] | WkT[NY_][NH_] | Us[CH_][NU_]   (~33KB)
// Phase B: warp tg -> 2 timesteps; lane owns k-pairs {64j + 2*lane, +1}
//          16-value butterfly allreduce -> direct STG (no Rd)
// =====================================================================
#define SM3_U64 (CH_ * XROW_ + NY_ * NH_ + CH_ * NU_)
#define SM3_BYTES (SM3_U64 * 8)

__global__ void __launch_bounds__(128, 5) k_main(
    const float* __restrict__ U,
    const float* __restrict__ Wxy, const float* __restrict__ bxy,
    float* __restrict__ Y)
{
    extern __shared__ __align__(16) u64 sm[];
    u64* Xs  = sm;                        // [CH_][XROW_], col k: 2h->x1, 2h+1->x2
    u64* WkT = sm + CH_ * XROW_;          // [NY_][NH_] transposed, interleaved cols
    u64* Us  = WkT + NY_ * NH_;           // [CH_][NU_]

    const int tid = threadIdx.x;
    const int h   = tid;
    const int bp  = blockIdx.x;
    const int s   = blockIdx.y;
    const int b0  = bp << 1;

    // prepack W transposed: WkT[y][k] = splat(Wxy[y][colmap(k)])
#pragma unroll
    for (int i = 0; i < 16; ++i) {
        int idx = tid * 16 + i;          // 0..2047
        int y = idx >> 8, k = idx & 255;
        int hh = k >> 1;
        int col = (k & 1) ? (hh + H2_) : hh;
        WkT[y * NH_ + k] = splat(Wxy[y * NH_ + col]);
    }

    float2 lm = g_lam[h];
    u64 re2 = splat(lm.x), im2 = splat(lm.y), ni2 = splat(-lm.y);

    u64 x1 = g_init[s][bp][h][0];
    u64 x2 = g_init[s][bp][h][1];

    // phase-B roles
    const int lane = tid & 31;
    const int tg   = tid >> 5;           // warp -> 2 timesteps
    const int tt   = (lane >> 4) & 1;    // owned t within warp pair (post-reduce)
    const int oy   = (lane >> 1) & 7;    // owned y (post-reduce)
    const u64 biasp = splat(bxy[oy]);

    const float* Ub = U + ((size_t)s * L_ * NB_ + b0) * NU_;

    for (int c = 0; c < NCH_; ++c) {
        __syncthreads();                 // prev-chunk Xs reads done before rewrite
        if (tid < CH_ * NU_) {
            int t = tid >> 3, u = tid & 7;
            const float* p = Ub + (size_t)(c * CH_ + t) * (NB_ * NU_) + u;
            Us[t * NU_ + u] = pk2(p[0], p[NU_]);
        }
        __syncthreads();

        // reload B splats per chunk (keeps them dead during phase B -> low regs)
        u64 Bp1[NU_], Bp2[NU_];
        {
            const ulonglong2* p1 = (const ulonglong2*)g_B1p[h];
            const ulonglong2* p2 = (const ulonglong2*)g_B2p[h];
            ulonglong2 a0 = p1[0], a1 = p1[1], a2 = p1[2], a3 = p1[3];
            ulonglong2 c0 = p2[0], c1 = p2[1], c2 = p2[2], c3 = p2[3];
            Bp1[0]=a0.x; Bp1[1]=a0.y; Bp1[2]=a1.x; Bp1[3]=a1.y;
            Bp1[4]=a2.x; Bp1[5]=a2.y; Bp1[6]=a3.x; Bp1[7]=a3.y;
            Bp2[0]=c0.x; Bp2[1]=c0.y; Bp2[2]=c1.x; Bp2[3]=c1.y;
            Bp2[4]=c2.x; Bp2[5]=c2.y; Bp2[6]=c3.x; Bp2[7]=c3.y;
        }

        // ---- phase A: scan CH_ steps, stash states in shared ----
#pragma unroll
        for (int t = 0; t < CH_; ++t) {
            const ulonglong2* up = (const ulonglong2*)(Us + t * NU_);
            ulonglong2 ua = up[0], ub = up[1], uc = up[2], ud = up[3];
            u64 uu[8] = { ua.x, ua.y, ub.x, ub.y, uc.x, uc.y, ud.x, ud.y };
            u64 bu1 = fmul2(Bp1[0], uu[0]);
            u64 bu2 = fmul2(Bp2[0], uu[0]);
#pragma unroll
            for (int u = 1; u < NU_; ++u) {
                bu1 = ffma2(Bp1[u], uu[u], bu1);
                bu2 = ffma2(Bp2[u], uu[u], bu2);
            }
            u64 nx1 = ffma2(re2, x1, ffma2(ni2, x2, bu1));
            u64 nx2 = ffma2(re2, x2, ffma2(im2, x1, bu2));
            x1 = nx1; x2 = nx2;
            *((ulonglong2*)(Xs + (size_t)t * XROW_ + 2 * h)) = make_ulonglong2(x1, x2);
        }
        __syncthreads();

        // ---- phase B: Y GEMM; acc[v], v = tloc*8 + y ----
        u64 acc[16];
#pragma unroll
        for (int v = 0; v < 16; ++v) acc[v] = 0ull;

        const u64* xrow0 = Xs + (size_t)(tg * 2 + 0) * XROW_;
        const u64* xrow1 = Xs + (size_t)(tg * 2 + 1) * XROW_;

#pragma unroll
        for (int j = 0; j < 4; ++j) {
            const int kb = j * 64 + 2 * lane;
            ulonglong2 xp0 = *((const ulonglong2*)(xrow0 + kb));
            ulonglong2 xp1 = *((const ulonglong2*)(xrow1 + kb));
#pragma unroll
            for (int y = 0; y < NY_; ++y) {
                ulonglong2 w = *((const ulonglong2*)(WkT + (size_t)y * NH_ + kb));
                acc[y]     = ffma2(w.x, xp0.x, ffma2(w.y, xp0.y, acc[y]));
                acc[8 + y] = ffma2(w.x, xp1.x, ffma2(w.y, xp1.y, acc[8 + y]));
            }
        }

        // ---- butterfly allreduce: 16 values over 32 lanes ----
        {
            int n = 16;
#pragma unroll
            for (int d = 16; d >= 2; d >>= 1) {
                n >>= 1;                 // 8,4,2,1
                const bool hi = (lane & d) != 0;
#pragma unroll
                for (int i = 0; i < 8; ++i) {
                    if (i < n) {
                        u64 snd = hi ? acc[i] : acc[i + n];
                        u64 rcv = __shfl_xor_sync(0xFFFFFFFFu, snd, d);
                        u64 kp  = hi ? acc[i + n] : acc[i];
                        acc[i] = fadd2(kp, rcv);
                    }
                }
            }
            // final pair reduce (lanes l, l^1 share the same output)
            acc[0] = fadd2(acc[0], __shfl_xor_sync(0xFFFFFFFFu, acc[0], 1));
        }

        if ((lane & 1) == 0) {
            u64 r = fadd2(acc[0], biasp);
            float f0, f1; upk2(r, f0, f1);
            int tgl = s * L_ + c * CH_ + tg * 2 + tt;
            float* yp = Y + ((size_t)tgl * NB_ + b0) * NY_ + oy;
            yp[0]   = f0;
            yp[NY_] = f1;
        }
    }
}

// =====================================================================
extern "C" void kernel_launch(void* const* d_in, const int* in_sizes, int n_in,
                              void* d_out, int out_size)
{
    const float* y0  = (const float*)d_in[0];
    const float* U   = (const float*)d_in[1];
    const float* lr  = (const float*)d_in[2];
    const float* li  = (const float*)d_in[3];
    const float* B   = (const float*)d_in[4];
    const float* mB  = (const float*)d_in[5];
    const float* Wyx = (const float*)d_in[6];
    const float* byx = (const float*)d_in[7];
    const float* Wxy = (const float*)d_in[8];
    const float* bxy = (const float*)d_in[9];
    float* Y = (float*)d_out;

    cudaFuncSetAttribute(k_main, cudaFuncAttributeMaxDynamicSharedMemorySize, SM3_BYTES);

    dim3 grid(NBP_, S_);
    k_pre <<<8, 16>>>(lr, li, B, mB);
    k_seg <<<grid, 128>>>(U);
    k_comb<<<NBP_, 128>>>(y0, Wyx, byx);
    k_main<<<grid, 128, SM3_BYTES>>>(U, Wxy, bxy, Y);
}